// round 2
// baseline (speedup 1.0000x reference)
#include <cuda_runtime.h>
#include <cuda_bf16.h>
#include <math.h>

// Problem dims (fixed)
#define BB 8
#define SS 1024
#define DD 768
#define LL 12
#define HH 12
#define HDD 64
#define FF_ 3072
#define MTOK (BB*SS)   // 8192 rows

// ---------------- scratch (device globals; no cudaMalloc allowed) ------------
__device__ float g_h   [MTOK*DD];
__device__ float g_q   [MTOK*DD];
__device__ float g_k   [MTOK*DD];
__device__ float g_v   [MTOK*DD];
__device__ float g_ctx [MTOK*DD];
__device__ float g_tmp [MTOK*DD];
__device__ float g_aout[MTOK*DD];
__device__ float g_int [MTOK*FF_];

// ---------------- block reduce --------------------------------------------
__device__ __forceinline__ float blockReduceSum(float val) {
    __shared__ float sh[32];
    int lane = threadIdx.x & 31, wid = threadIdx.x >> 5;
#pragma unroll
    for (int o = 16; o > 0; o >>= 1) val += __shfl_xor_sync(0xffffffffu, val, o);
    __syncthreads();                 // protect sh across repeated calls
    if (lane == 0) sh[wid] = val;
    __syncthreads();
    if (wid == 0) {
        float v2 = (lane < (int)(blockDim.x >> 5)) ? sh[lane] : 0.f;
#pragma unroll
        for (int o = 4; o > 0; o >>= 1) v2 += __shfl_xor_sync(0xffffffffu, v2, o);
        if (lane == 0) sh[0] = v2;
    }
    __syncthreads();
    return sh[0];
}

// ---------------- embeddings + LN -----------------------------------------
__global__ __launch_bounds__(256) void embed_kernel(
    const int* __restrict__ ids, const float* __restrict__ we,
    const float* __restrict__ pe, const float* __restrict__ te,
    const float* __restrict__ gam, const float* __restrict__ bet,
    float* __restrict__ H)
{
    int row = blockIdx.x;            // b*S + s
    int s   = row & (SS - 1);
    int tid = threadIdx.x;
    int id  = ids[row];
    size_t base = (size_t)row * DD;
    const float* wrow = we + (size_t)id * DD;
    const float* prow = pe + (size_t)s * DD;
    float v[3]; float lsum = 0.f;
#pragma unroll
    for (int c = 0; c < 3; c++) {
        int d = tid + c * 256;
        v[c] = wrow[d] + prow[d] + te[d];
        lsum += v[c];
    }
    float mean = blockReduceSum(lsum) * (1.0f / DD);
    float lsq = 0.f;
#pragma unroll
    for (int c = 0; c < 3; c++) { float t = v[c] - mean; lsq += t * t; }
    float var = blockReduceSum(lsq) * (1.0f / DD);
    float rstd = rsqrtf(var + 1e-12f);
#pragma unroll
    for (int c = 0; c < 3; c++) {
        int d = tid + c * 256;
        H[base + d] = (v[c] - mean) * rstd * gam[d] + bet[d];
    }
}

// ---------------- residual add + LN ----------------------------------------
__global__ __launch_bounds__(256) void add_ln_kernel(
    const float* __restrict__ X, const float* __restrict__ R,
    const float* __restrict__ gam, const float* __restrict__ bet,
    float* __restrict__ Y)
{
    int row = blockIdx.x;
    int tid = threadIdx.x;
    size_t base = (size_t)row * DD;
    float v[3]; float lsum = 0.f;
#pragma unroll
    for (int c = 0; c < 3; c++) {
        int d = tid + c * 256;
        v[c] = X[base + d] + R[base + d];
        lsum += v[c];
    }
    float mean = blockReduceSum(lsum) * (1.0f / DD);
    float lsq = 0.f;
#pragma unroll
    for (int c = 0; c < 3; c++) { float t = v[c] - mean; lsq += t * t; }
    float var = blockReduceSum(lsq) * (1.0f / DD);
    float rstd = rsqrtf(var + 1e-12f);
#pragma unroll
    for (int c = 0; c < 3; c++) {
        int d = tid + c * 256;
        Y[base + d] = (v[c] - mean) * rstd * gam[d] + bet[d];
    }
}

// ---------------- fp32 tiled GEMM (double-buffered) -------------------------
// C = A[M,K] @ W[K,N] + bias, opt. GELU. BM=BN=128, BK=16, 256 thr, 8x8 micro.
__global__ __launch_bounds__(256, 2) void gemm_kernel(
    const float* __restrict__ A, const float* __restrict__ W,
    const float* __restrict__ bias, float* __restrict__ C,
    int M, int N, int K, int act)
{
    __shared__ __align__(16) float As[2][16][128];
    __shared__ __align__(16) float Ws[2][16][128];
    int tid = threadIdx.x;
    int tx = tid & 15, ty = tid >> 4;
    int m0 = blockIdx.y * 128, n0 = blockIdx.x * 128;

    // per-thread load slots: A -> 2 float4 (transposed store), W -> 2 float4
    int aM[2], aK[2];
    int wK[2], wN[2];
#pragma unroll
    for (int u = 0; u < 2; u++) {
        int i = tid + u * 256;
        aM[u] = i >> 2; aK[u] = (i & 3) << 2;
        wK[u] = i >> 5; wN[u] = (i & 31) << 2;
    }

    float acc[8][8];
#pragma unroll
    for (int i = 0; i < 8; i++)
#pragma unroll
        for (int j = 0; j < 8; j++) acc[i][j] = 0.f;

    int nkt = K >> 4;
    // preload tile 0
    float4 ra[2], rw[2];
#pragma unroll
    for (int u = 0; u < 2; u++) {
        ra[u] = *(const float4*)&A[(size_t)(m0 + aM[u]) * K + aK[u]];
        rw[u] = *(const float4*)&W[(size_t)wK[u] * N + n0 + wN[u]];
    }
#pragma unroll
    for (int u = 0; u < 2; u++) {
        As[0][aK[u] + 0][aM[u]] = ra[u].x; As[0][aK[u] + 1][aM[u]] = ra[u].y;
        As[0][aK[u] + 2][aM[u]] = ra[u].z; As[0][aK[u] + 3][aM[u]] = ra[u].w;
        *(float4*)&Ws[0][wK[u]][wN[u]] = rw[u];
    }
    __syncthreads();

    for (int kt = 0; kt < nkt; kt++) {
        int cur = kt & 1;
        if (kt + 1 < nkt) {
            int kb = (kt + 1) << 4;
#pragma unroll
            for (int u = 0; u < 2; u++) {
                ra[u] = *(const float4*)&A[(size_t)(m0 + aM[u]) * K + kb + aK[u]];
                rw[u] = *(const float4*)&W[(size_t)(kb + wK[u]) * N + n0 + wN[u]];
            }
        }
#pragma unroll
        for (int kk = 0; kk < 16; kk++) {
            float4 a0 = *(float4*)&As[cur][kk][ty * 8];
            float4 a1 = *(float4*)&As[cur][kk][ty * 8 + 4];
            float4 b0 = *(float4*)&Ws[cur][kk][tx * 8];
            float4 b1 = *(float4*)&Ws[cur][kk][tx * 8 + 4];
            float av[8] = {a0.x, a0.y, a0.z, a0.w, a1.x, a1.y, a1.z, a1.w};
            float bv[8] = {b0.x, b0.y, b0.z, b0.w, b1.x, b1.y, b1.z, b1.w};
#pragma unroll
            for (int i = 0; i < 8; i++)
#pragma unroll
                for (int j = 0; j < 8; j++) acc[i][j] += av[i] * bv[j];
        }
        if (kt + 1 < nkt) {
            int nxt = cur ^ 1;
#pragma unroll
            for (int u = 0; u < 2; u++) {
                As[nxt][aK[u] + 0][aM[u]] = ra[u].x; As[nxt][aK[u] + 1][aM[u]] = ra[u].y;
                As[nxt][aK[u] + 2][aM[u]] = ra[u].z; As[nxt][aK[u] + 3][aM[u]] = ra[u].w;
                *(float4*)&Ws[nxt][wK[u]][wN[u]] = rw[u];
            }
            __syncthreads();
        }
    }
    // epilogue
#pragma unroll
    for (int i = 0; i < 8; i++) {
        int m = m0 + ty * 8 + i;
#pragma unroll
        for (int jj = 0; jj < 8; jj += 4) {
            float4 o;
            float* op = &o.x;
#pragma unroll
            for (int j = 0; j < 4; j++) {
                int n = n0 + tx * 8 + jj + j;
                float c = acc[i][jj + j] + bias[n];
                if (act) c = 0.5f * c * (1.0f + erff(c * 0.70710678118654752f));
                op[j] = c;
            }
            *(float4*)&C[(size_t)m * N + n0 + tx * 8 + jj] = o;
        }
    }
}

// ---- fused QKV variant: gridDim.z = 3 selects (W,b,out) ---------------------
__global__ __launch_bounds__(256, 2) void gemm_qkv_kernel(
    const float* __restrict__ A,
    const float* __restrict__ Wq, const float* __restrict__ Wk, const float* __restrict__ Wv,
    const float* __restrict__ bq, const float* __restrict__ bk, const float* __restrict__ bv,
    float* __restrict__ Oq, float* __restrict__ Ok, float* __restrict__ Ov)
{
    const float* W; const float* bias; float* C;
    if (blockIdx.z == 0)      { W = Wq; bias = bq; C = Oq; }
    else if (blockIdx.z == 1) { W = Wk; bias = bk; C = Ok; }
    else                      { W = Wv; bias = bv; C = Ov; }
    const int K = DD, N = DD;

    __shared__ __align__(16) float As[2][16][128];
    __shared__ __align__(16) float Ws[2][16][128];
    int tid = threadIdx.x;
    int tx = tid & 15, ty = tid >> 4;
    int m0 = blockIdx.y * 128, n0 = blockIdx.x * 128;

    int aM[2], aK[2], wK[2], wN[2];
#pragma unroll
    for (int u = 0; u < 2; u++) {
        int i = tid + u * 256;
        aM[u] = i >> 2; aK[u] = (i & 3) << 2;
        wK[u] = i >> 5; wN[u] = (i & 31) << 2;
    }

    float acc[8][8];
#pragma unroll
    for (int i = 0; i < 8; i++)
#pragma unroll
        for (int j = 0; j < 8; j++) acc[i][j] = 0.f;

    const int nkt = K >> 4;
    float4 ra[2], rw[2];
#pragma unroll
    for (int u = 0; u < 2; u++) {
        ra[u] = *(const float4*)&A[(size_t)(m0 + aM[u]) * K + aK[u]];
        rw[u] = *(const float4*)&W[(size_t)wK[u] * N + n0 + wN[u]];
    }
#pragma unroll
    for (int u = 0; u < 2; u++) {
        As[0][aK[u] + 0][aM[u]] = ra[u].x; As[0][aK[u] + 1][aM[u]] = ra[u].y;
        As[0][aK[u] + 2][aM[u]] = ra[u].z; As[0][aK[u] + 3][aM[u]] = ra[u].w;
        *(float4*)&Ws[0][wK[u]][wN[u]] = rw[u];
    }
    __syncthreads();

    for (int kt = 0; kt < nkt; kt++) {
        int cur = kt & 1;
        if (kt + 1 < nkt) {
            int kb = (kt + 1) << 4;
#pragma unroll
            for (int u = 0; u < 2; u++) {
                ra[u] = *(const float4*)&A[(size_t)(m0 + aM[u]) * K + kb + aK[u]];
                rw[u] = *(const float4*)&W[(size_t)(kb + wK[u]) * N + n0 + wN[u]];
            }
        }
#pragma unroll
        for (int kk = 0; kk < 16; kk++) {
            float4 a0 = *(float4*)&As[cur][kk][ty * 8];
            float4 a1 = *(float4*)&As[cur][kk][ty * 8 + 4];
            float4 b0 = *(float4*)&Ws[cur][kk][tx * 8];
            float4 b1 = *(float4*)&Ws[cur][kk][tx * 8 + 4];
            float av[8] = {a0.x, a0.y, a0.z, a0.w, a1.x, a1.y, a1.z, a1.w};
            float bv[8] = {b0.x, b0.y, b0.z, b0.w, b1.x, b1.y, b1.z, b1.w};
#pragma unroll
            for (int i = 0; i < 8; i++)
#pragma unroll
                for (int j = 0; j < 8; j++) acc[i][j] += av[i] * bv[j];
        }
        if (kt + 1 < nkt) {
            int nxt = cur ^ 1;
#pragma unroll
            for (int u = 0; u < 2; u++) {
                As[nxt][aK[u] + 0][aM[u]] = ra[u].x; As[nxt][aK[u] + 1][aM[u]] = ra[u].y;
                As[nxt][aK[u] + 2][aM[u]] = ra[u].z; As[nxt][aK[u] + 3][aM[u]] = ra[u].w;
                *(float4*)&Ws[nxt][wK[u]][wN[u]] = rw[u];
            }
            __syncthreads();
        }
    }
#pragma unroll
    for (int i = 0; i < 8; i++) {
        int m = m0 + ty * 8 + i;
#pragma unroll
        for (int jj = 0; jj < 8; jj += 4) {
            float4 o;
            float* op = &o.x;
#pragma unroll
            for (int j = 0; j < 4; j++) {
                int n = n0 + tx * 8 + jj + j;
                op[j] = acc[i][jj + j] + bias[n];
            }
            *(float4*)&C[(size_t)m * N + n0 + tx * 8 + jj] = o;
        }
    }
}

// ---------------- flash attention (masked softmax), HD=64 ------------------
// grid: (S/64, B*H); block 256 (16x16); each thread: 4q x 4k scores, 4q x 4d out
#define AT_STR 68
#define AT_SMEM (4 * 64 * AT_STR * 4)
__global__ __launch_bounds__(256, 2) void attn_kernel(
    const float* __restrict__ Q, const float* __restrict__ K,
    const float* __restrict__ V, const int* __restrict__ amask,
    float* __restrict__ ctx)
{
    extern __shared__ float sm[];
    float* Qt = sm;                    // [64][AT_STR]  (d-major, transposed)
    float* Kt = sm + 64 * AT_STR;      // [64][AT_STR]
    float* Vs = sm + 2 * 64 * AT_STR;  // [64][AT_STR]  (k-major, natural)
    float* Pt = sm + 3 * 64 * AT_STR;  // [64][AT_STR]  (k-major, transposed)
    __shared__ float mbias[64];

    int tid = threadIdx.x;
    int tx = tid & 15, ty = tid >> 4;
    int bh = blockIdx.y;
    int b = bh / HH, h = bh % HH;
    int q0 = blockIdx.x * 64;

    size_t baseq = ((size_t)(b * SS + q0)) * DD + h * HDD;
    for (int i = tid; i < 64 * 16; i += 256) {
        int q = i >> 4; int dq = (i & 15) << 2;
        float4 a = *(const float4*)&Q[baseq + (size_t)q * DD + dq];
        Qt[(dq + 0) * AT_STR + q] = a.x; Qt[(dq + 1) * AT_STR + q] = a.y;
        Qt[(dq + 2) * AT_STR + q] = a.z; Qt[(dq + 3) * AT_STR + q] = a.w;
    }
    float m_r[4], l_r[4], O[4][4];
#pragma unroll
    for (int i = 0; i < 4; i++) {
        m_r[i] = -1e30f; l_r[i] = 0.f;
#pragma unroll
        for (int j = 0; j < 4; j++) O[i][j] = 0.f;
    }
    __syncthreads();

    for (int kc = 0; kc < SS / 64; kc++) {
        int k0 = kc * 64;
        size_t basek = ((size_t)(b * SS + k0)) * DD + h * HDD;
        for (int i = tid; i < 64 * 16; i += 256) {
            int k = i >> 4; int dq = (i & 15) << 2;
            float4 a = *(const float4*)&K[basek + (size_t)k * DD + dq];
            Kt[(dq + 0) * AT_STR + k] = a.x; Kt[(dq + 1) * AT_STR + k] = a.y;
            Kt[(dq + 2) * AT_STR + k] = a.z; Kt[(dq + 3) * AT_STR + k] = a.w;
            float4 vv = *(const float4*)&V[basek + (size_t)k * DD + dq];
            *(float4*)&Vs[k * AT_STR + dq] = vv;
        }
        if (tid < 64) mbias[tid] = amask[b * SS + k0 + tid] ? 0.f : -1e30f;
        __syncthreads();

        // scores: S = Q @ K^T over d
        float s[4][4];
#pragma unroll
        for (int i = 0; i < 4; i++)
#pragma unroll
            for (int j = 0; j < 4; j++) s[i][j] = 0.f;
#pragma unroll 8
        for (int kk = 0; kk < 64; kk++) {
            float4 qa = *(float4*)&Qt[kk * AT_STR + ty * 4];
            float4 kb = *(float4*)&Kt[kk * AT_STR + tx * 4];
            float qv[4] = {qa.x, qa.y, qa.z, qa.w};
            float kv[4] = {kb.x, kb.y, kb.z, kb.w};
#pragma unroll
            for (int i = 0; i < 4; i++)
#pragma unroll
                for (int j = 0; j < 4; j++) s[i][j] += qv[i] * kv[j];
        }
        float mb[4];
#pragma unroll
        for (int j = 0; j < 4; j++) mb[j] = mbias[tx * 4 + j];
#pragma unroll
        for (int i = 0; i < 4; i++)
#pragma unroll
            for (int j = 0; j < 4; j++) s[i][j] = s[i][j] * 0.125f + mb[j];

        // online softmax update (row groups = 16 lanes sharing ty)
#pragma unroll
        for (int i = 0; i < 4; i++) {
            float mx = fmaxf(fmaxf(s[i][0], s[i][1]), fmaxf(s[i][2], s[i][3]));
#pragma unroll
            for (int o = 8; o > 0; o >>= 1) mx = fmaxf(mx, __shfl_xor_sync(0xffffffffu, mx, o));
            float mnew = fmaxf(m_r[i], mx);
            float alpha = __expf(m_r[i] - mnew);
            float rs = 0.f;
#pragma unroll
            for (int j = 0; j < 4; j++) { s[i][j] = __expf(s[i][j] - mnew); rs += s[i][j]; }
#pragma unroll
            for (int o = 8; o > 0; o >>= 1) rs += __shfl_xor_sync(0xffffffffu, rs, o);
            l_r[i] = l_r[i] * alpha + rs;
            m_r[i] = mnew;
#pragma unroll
            for (int j = 0; j < 4; j++) O[i][j] *= alpha;
        }
        // write P transposed: Pt[k][q]
#pragma unroll
        for (int i = 0; i < 4; i++)
#pragma unroll
            for (int j = 0; j < 4; j++)
                Pt[(tx * 4 + j) * AT_STR + ty * 4 + i] = s[i][j];
        __syncthreads();

        // O += P @ V over k
#pragma unroll 8
        for (int kk = 0; kk < 64; kk++) {
            float4 pa = *(float4*)&Pt[kk * AT_STR + ty * 4];
            float4 vb = *(float4*)&Vs[kk * AT_STR + tx * 4];
            float pv[4] = {pa.x, pa.y, pa.z, pa.w};
            float vv[4] = {vb.x, vb.y, vb.z, vb.w};
#pragma unroll
            for (int i = 0; i < 4; i++)
#pragma unroll
                for (int j = 0; j < 4; j++) O[i][j] += pv[i] * vv[j];
        }
        __syncthreads();
    }
    // write ctx (merge heads)
    size_t baseo = ((size_t)(b * SS + q0)) * DD + h * HDD;
#pragma unroll
    for (int i = 0; i < 4; i++) {
        float inv = 1.0f / l_r[i];
#pragma unroll
        for (int j = 0; j < 4; j++)
            ctx[baseo + (size_t)(ty * 4 + i) * DD + tx * 4 + j] = O[i][j] * inv;
    }
}

// ---------------- masked mean pool + L2 normalize --------------------------
__global__ __launch_bounds__(256) void pool_kernel(
    const float* __restrict__ H, const int* __restrict__ amask,
    float* __restrict__ out)
{
    int b = blockIdx.x;
    int tid = threadIdx.x;
    float acc[3] = {0.f, 0.f, 0.f};
    float cl = 0.f;
    for (int s = tid; s < SS; s += 256) cl += (float)amask[b * SS + s];
    float cnt = blockReduceSum(cl);
    for (int s = 0; s < SS; s++) {
        if (amask[b * SS + s]) {
            size_t base = ((size_t)(b * SS + s)) * DD;
#pragma unroll
            for (int c = 0; c < 3; c++) acc[c] += H[base + tid + c * 256];
        }
    }
    float inv = 1.0f / fmaxf(cnt, 1e-6f);
    float se[3]; float lsq = 0.f;
#pragma unroll
    for (int c = 0; c < 3; c++) { se[c] = acc[c] * inv; lsq += se[c] * se[c]; }
    float ss = blockReduceSum(lsq);
    float nrm = sqrtf(ss);
    float d = 1.0f / fmaxf(nrm, 1e-12f);
#pragma unroll
    for (int c = 0; c < 3; c++) out[b * DD + tid + c * 256] = se[c] * d;
}

// ---------------- launch ----------------------------------------------------
extern "C" void kernel_launch(void* const* d_in, const int* in_sizes, int n_in,
                              void* d_out, int out_size)
{
    const int*   ids   = (const int*)  d_in[0];
    const int*   amask = (const int*)  d_in[1];
    const float* we    = (const float*)d_in[2];
    const float* pe    = (const float*)d_in[3];
    const float* te    = (const float*)d_in[4];
    const float* es    = (const float*)d_in[5];
    const float* eb    = (const float*)d_in[6];
    const float* Wq    = (const float*)d_in[7];
    const float* bq    = (const float*)d_in[8];
    const float* Wk    = (const float*)d_in[9];
    const float* bk    = (const float*)d_in[10];
    const float* Wv    = (const float*)d_in[11];
    const float* bv    = (const float*)d_in[12];
    const float* Wao   = (const float*)d_in[13];
    const float* bao   = (const float*)d_in[14];
    const float* ln1s  = (const float*)d_in[15];
    const float* ln1b  = (const float*)d_in[16];
    const float* Wi    = (const float*)d_in[17];
    const float* bi    = (const float*)d_in[18];
    const float* Wmo   = (const float*)d_in[19];
    const float* bmo   = (const float*)d_in[20];
    const float* ln2s  = (const float*)d_in[21];
    const float* ln2b  = (const float*)d_in[22];
    float* out = (float*)d_out;

    float *h, *q, *k, *v, *ctx, *tmp, *aout, *inter;
    cudaGetSymbolAddress((void**)&h,     g_h);
    cudaGetSymbolAddress((void**)&q,     g_q);
    cudaGetSymbolAddress((void**)&k,     g_k);
    cudaGetSymbolAddress((void**)&v,     g_v);
    cudaGetSymbolAddress((void**)&ctx,   g_ctx);
    cudaGetSymbolAddress((void**)&tmp,   g_tmp);
    cudaGetSymbolAddress((void**)&aout,  g_aout);
    cudaGetSymbolAddress((void**)&inter, g_int);

    cudaFuncSetAttribute(attn_kernel, cudaFuncAttributeMaxDynamicSharedMemorySize, AT_SMEM);

    embed_kernel<<<MTOK, 256>>>(ids, we, pe, te, es, eb, h);

    for (int l = 0; l < LL; l++) {
        const float* wq  = Wq  + (size_t)l * DD * DD;
        const float* wk  = Wk  + (size_t)l * DD * DD;
        const float* wv  = Wv  + (size_t)l * DD * DD;
        const float* wao = Wao + (size_t)l * DD * DD;
        const float* wi  = Wi  + (size_t)l * DD * FF_;
        const float* wmo = Wmo + (size_t)l * FF_ * DD;
        const float* bqL  = bq  + (size_t)l * DD;
        const float* bkL  = bk  + (size_t)l * DD;
        const float* bvL  = bv  + (size_t)l * DD;
        const float* baoL = bao + (size_t)l * DD;
        const float* biL  = bi  + (size_t)l * FF_;
        const float* bmoL = bmo + (size_t)l * DD;
        const float* l1s = ln1s + (size_t)l * DD;
        const float* l1b = ln1b + (size_t)l * DD;
        const float* l2s = ln2s + (size_t)l * DD;
        const float* l2b = ln2b + (size_t)l * DD;

        dim3 gD(DD / 128, MTOK / 128);        // (6, 64)
        dim3 gQKV(DD / 128, MTOK / 128, 3);   // (6, 64, 3)
        dim3 gF(FF_ / 128, MTOK / 128);       // (24, 64)

        gemm_qkv_kernel<<<gQKV, 256>>>(h, wq, wk, wv, bqL, bkL, bvL, q, k, v);

        attn_kernel<<<dim3(SS / 64, BB * HH), 256, AT_SMEM>>>(q, k, v, amask, ctx);

        gemm_kernel<<<gD, 256>>>(ctx, wao, baoL, tmp, MTOK, DD, DD, 0);
        add_ln_kernel<<<MTOK, 256>>>(tmp, h, l1s, l1b, aout);

        gemm_kernel<<<gF, 256>>>(aout,  wi,  biL,  inter, MTOK, FF_, DD, 1);
        gemm_kernel<<<gD, 256>>>(inter, wmo, bmoL, tmp,   MTOK, DD, FF_, 0);
        add_ln_kernel<<<MTOK, 256>>>(tmp, aout, l2s, l2b, h);
    }

    pool_kernel<<<BB, 256>>>(h, amask, out);
}

// round 8
// speedup vs baseline: 3.1318x; 3.1318x over previous
#include <cuda_runtime.h>
#include <cuda_bf16.h>
#include <math.h>
#include <stdint.h>

// Problem dims (fixed)
#define BB 8
#define SS 1024
#define DD 768
#define LL 12
#define HH 12
#define HDD 64
#define FF_ 3072
#define MTOK (BB*SS)   // 8192 rows

// ---------------- scratch (device globals; no cudaMalloc allowed) ------------
__device__ float g_h   [MTOK*DD];
__device__ float g_q   [MTOK*DD];
__device__ float g_k   [MTOK*DD];
__device__ float g_v   [MTOK*DD];
__device__ float g_ctx [MTOK*DD];
__device__ float g_tmp [MTOK*DD];
__device__ float g_aout[MTOK*DD];
__device__ float g_int [MTOK*FF_];

// ---------------- block reduce --------------------------------------------
__device__ __forceinline__ float blockReduceSum(float val) {
    __shared__ float sh[32];
    int lane = threadIdx.x & 31, wid = threadIdx.x >> 5;
#pragma unroll
    for (int o = 16; o > 0; o >>= 1) val += __shfl_xor_sync(0xffffffffu, val, o);
    __syncthreads();
    if (lane == 0) sh[wid] = val;
    __syncthreads();
    if (wid == 0) {
        float v2 = (lane < (int)(blockDim.x >> 5)) ? sh[lane] : 0.f;
#pragma unroll
        for (int o = 4; o > 0; o >>= 1) v2 += __shfl_xor_sync(0xffffffffu, v2, o);
        if (lane == 0) sh[0] = v2;
    }
    __syncthreads();
    return sh[0];
}

// ---------------- embeddings + LN -----------------------------------------
__global__ __launch_bounds__(256) void embed_kernel(
    const int* __restrict__ ids, const float* __restrict__ we,
    const float* __restrict__ pe, const float* __restrict__ te,
    const float* __restrict__ gam, const float* __restrict__ bet,
    float* __restrict__ H)
{
    int row = blockIdx.x;
    int s   = row & (SS - 1);
    int tid = threadIdx.x;
    int id  = ids[row];
    size_t base = (size_t)row * DD;
    const float* wrow = we + (size_t)id * DD;
    const float* prow = pe + (size_t)s * DD;
    float v[3]; float lsum = 0.f;
#pragma unroll
    for (int c = 0; c < 3; c++) {
        int d = tid + c * 256;
        v[c] = wrow[d] + prow[d] + te[d];
        lsum += v[c];
    }
    float mean = blockReduceSum(lsum) * (1.0f / DD);
    float lsq = 0.f;
#pragma unroll
    for (int c = 0; c < 3; c++) { float t = v[c] - mean; lsq += t * t; }
    float var = blockReduceSum(lsq) * (1.0f / DD);
    float rstd = rsqrtf(var + 1e-12f);
#pragma unroll
    for (int c = 0; c < 3; c++) {
        int d = tid + c * 256;
        H[base + d] = (v[c] - mean) * rstd * gam[d] + bet[d];
    }
}

// ---------------- residual add + LN ----------------------------------------
__global__ __launch_bounds__(256) void add_ln_kernel(
    const float* __restrict__ X, const float* __restrict__ R,
    const float* __restrict__ gam, const float* __restrict__ bet,
    float* __restrict__ Y)
{
    int row = blockIdx.x;
    int tid = threadIdx.x;
    size_t base = (size_t)row * DD;
    float v[3]; float lsum = 0.f;
#pragma unroll
    for (int c = 0; c < 3; c++) {
        int d = tid + c * 256;
        v[c] = X[base + d] + R[base + d];
        lsum += v[c];
    }
    float mean = blockReduceSum(lsum) * (1.0f / DD);
    float lsq = 0.f;
#pragma unroll
    for (int c = 0; c < 3; c++) { float t = v[c] - mean; lsq += t * t; }
    float var = blockReduceSum(lsq) * (1.0f / DD);
    float rstd = rsqrtf(var + 1e-12f);
#pragma unroll
    for (int c = 0; c < 3; c++) {
        int d = tid + c * 256;
        Y[base + d] = (v[c] - mean) * rstd * gam[d] + bet[d];
    }
}

// ---------------- TF32 tensor-core GEMM -------------------------------------
// C = A[M,K] @ W[K,N] + bias, opt. GELU.
// BM=BN=128, BK=32, 256 thr = 8 warps (2x4), warp tile 64x32, mma.m16n8k8.tf32.
#define APAD 36   // A smem row stride (floats): banks (g*4+tg) distinct
#define BPAD 136  // B smem row stride (floats): banks (tg*8+g) distinct
#define ATILE (128 * APAD)
#define BTILE (32 * BPAD)
#define GSMEM ((2 * (ATILE + BTILE)) * 4)   // bytes = 71680

__device__ __forceinline__ uint32_t f2tf32(float x) {
    uint32_t r;
    asm volatile("cvt.rna.tf32.f32 %0, %1;" : "=r"(r) : "f"(x));
    return r;
}
__device__ __forceinline__ void mma_tf32(float* c, uint32_t a0, uint32_t a1,
                                         uint32_t a2, uint32_t a3,
                                         uint32_t b0, uint32_t b1) {
    asm volatile(
        "mma.sync.aligned.m16n8k8.row.col.f32.tf32.tf32.f32 "
        "{%0,%1,%2,%3}, {%4,%5,%6,%7}, {%8,%9}, {%0,%1,%2,%3};\n"
        : "+f"(c[0]), "+f"(c[1]), "+f"(c[2]), "+f"(c[3])
        : "r"(a0), "r"(a1), "r"(a2), "r"(a3), "r"(b0), "r"(b1));
}

// Core body shared by generic and QKV kernels.
__device__ __forceinline__ void gemm_tf32_body(
    const float* __restrict__ A, const float* __restrict__ W,
    const float* __restrict__ bias, float* __restrict__ C,
    int M, int N, int K, int act, int m0, int n0, float* sm)
{
    float* As = sm;                       // [2][128][APAD]
    float* Bs = sm + 2 * ATILE;          // [2][32][BPAD]

    int tid  = threadIdx.x;
    int lane = tid & 31;
    int wrp  = tid >> 5;
    int wm   = wrp >> 2;        // 0..1 -> 64-row slab
    int wn   = wrp & 3;         // 0..3 -> 32-col slab
    int g    = lane >> 2;       // 0..7
    int tg   = lane & 3;        // 0..3

    // staging indices: A tile 128x32 (8 f4/row), B tile 32x128 (32 f4/row)
    int aR[4], aC[4], bR[4], bC[4];
#pragma unroll
    for (int u = 0; u < 4; u++) {
        int i = tid + u * 256;
        aR[u] = i >> 3;  aC[u] = (i & 7) << 2;
        bR[u] = i >> 5;  bC[u] = (i & 31) << 2;
    }

    float acc[4][4][4];
#pragma unroll
    for (int mt = 0; mt < 4; mt++)
#pragma unroll
        for (int nt = 0; nt < 4; nt++)
#pragma unroll
            for (int e = 0; e < 4; e++) acc[mt][nt][e] = 0.f;

    const int nkt = K >> 5;   // BK=32
    float4 ra[4], rw[4];
#pragma unroll
    for (int u = 0; u < 4; u++) {
        ra[u] = *(const float4*)&A[(size_t)(m0 + aR[u]) * K + aC[u]];
        rw[u] = *(const float4*)&W[(size_t)bR[u] * N + n0 + bC[u]];
    }
#pragma unroll
    for (int u = 0; u < 4; u++) {
        float* ap = &As[aR[u] * APAD + aC[u]];
        ap[0] = __uint_as_float(f2tf32(ra[u].x));
        ap[1] = __uint_as_float(f2tf32(ra[u].y));
        ap[2] = __uint_as_float(f2tf32(ra[u].z));
        ap[3] = __uint_as_float(f2tf32(ra[u].w));
        float* bp = &Bs[bR[u] * BPAD + bC[u]];
        bp[0] = __uint_as_float(f2tf32(rw[u].x));
        bp[1] = __uint_as_float(f2tf32(rw[u].y));
        bp[2] = __uint_as_float(f2tf32(rw[u].z));
        bp[3] = __uint_as_float(f2tf32(rw[u].w));
    }
    __syncthreads();

    for (int kt = 0; kt < nkt; kt++) {
        int cur = kt & 1;
        const float* Ac = As + cur * ATILE;
        const float* Bc = Bs + cur * BTILE;
        if (kt + 1 < nkt) {
            int kb = (kt + 1) << 5;
#pragma unroll
            for (int u = 0; u < 4; u++) {
                ra[u] = *(const float4*)&A[(size_t)(m0 + aR[u]) * K + kb + aC[u]];
                rw[u] = *(const float4*)&W[(size_t)(kb + bR[u]) * N + n0 + bC[u]];
            }
        }
#pragma unroll
        for (int ks = 0; ks < 4; ks++) {
            int k0 = ks << 3;
            uint32_t af[4][4];
#pragma unroll
            for (int mt = 0; mt < 4; mt++) {
                int r0 = wm * 64 + mt * 16 + g;
                af[mt][0] = __float_as_uint(Ac[(r0    ) * APAD + k0 + tg    ]);
                af[mt][1] = __float_as_uint(Ac[(r0 + 8) * APAD + k0 + tg    ]);
                af[mt][2] = __float_as_uint(Ac[(r0    ) * APAD + k0 + tg + 4]);
                af[mt][3] = __float_as_uint(Ac[(r0 + 8) * APAD + k0 + tg + 4]);
            }
            uint32_t bf[4][2];
#pragma unroll
            for (int nt = 0; nt < 4; nt++) {
                int c0 = wn * 32 + nt * 8 + g;
                bf[nt][0] = __float_as_uint(Bc[(k0 + tg    ) * BPAD + c0]);
                bf[nt][1] = __float_as_uint(Bc[(k0 + tg + 4) * BPAD + c0]);
            }
#pragma unroll
            for (int mt = 0; mt < 4; mt++)
#pragma unroll
                for (int nt = 0; nt < 4; nt++)
                    mma_tf32(acc[mt][nt], af[mt][0], af[mt][1], af[mt][2], af[mt][3],
                             bf[nt][0], bf[nt][1]);
        }
        if (kt + 1 < nkt) {
            int nxt = cur ^ 1;
            float* An = As + nxt * ATILE;
            float* Bn = Bs + nxt * BTILE;
#pragma unroll
            for (int u = 0; u < 4; u++) {
                float* ap = &An[aR[u] * APAD + aC[u]];
                ap[0] = __uint_as_float(f2tf32(ra[u].x));
                ap[1] = __uint_as_float(f2tf32(ra[u].y));
                ap[2] = __uint_as_float(f2tf32(ra[u].z));
                ap[3] = __uint_as_float(f2tf32(ra[u].w));
                float* bp = &Bn[bR[u] * BPAD + bC[u]];
                bp[0] = __uint_as_float(f2tf32(rw[u].x));
                bp[1] = __uint_as_float(f2tf32(rw[u].y));
                bp[2] = __uint_as_float(f2tf32(rw[u].z));
                bp[3] = __uint_as_float(f2tf32(rw[u].w));
            }
            __syncthreads();
        }
    }

    // epilogue: row = m0+wm*64+mt*16+g(+8), col = n0+wn*32+nt*8+tg*2(+1)
#pragma unroll
    for (int mt = 0; mt < 4; mt++) {
        int r0 = m0 + wm * 64 + mt * 16 + g;
#pragma unroll
        for (int nt = 0; nt < 4; nt++) {
            int c0 = n0 + wn * 32 + nt * 8 + tg * 2;
            float b0 = bias[c0], b1 = bias[c0 + 1];
            float v0 = acc[mt][nt][0] + b0;
            float v1 = acc[mt][nt][1] + b1;
            float v2 = acc[mt][nt][2] + b0;
            float v3 = acc[mt][nt][3] + b1;
            if (act) {
                v0 = 0.5f * v0 * (1.0f + erff(v0 * 0.70710678118654752f));
                v1 = 0.5f * v1 * (1.0f + erff(v1 * 0.70710678118654752f));
                v2 = 0.5f * v2 * (1.0f + erff(v2 * 0.70710678118654752f));
                v3 = 0.5f * v3 * (1.0f + erff(v3 * 0.70710678118654752f));
            }
            *(float2*)&C[(size_t)r0 * N + c0]       = make_float2(v0, v1);
            *(float2*)&C[(size_t)(r0 + 8) * N + c0] = make_float2(v2, v3);
        }
    }
}

__global__ __launch_bounds__(256, 2) void gemm_tf32_kernel(
    const float* __restrict__ A, const float* __restrict__ W,
    const float* __restrict__ bias, float* __restrict__ C,
    int M, int N, int K, int act)
{
    extern __shared__ float sm[];
    gemm_tf32_body(A, W, bias, C, M, N, K, act,
                   blockIdx.y * 128, blockIdx.x * 128, sm);
}

__global__ __launch_bounds__(256, 2) void gemm_tf32_qkv_kernel(
    const float* __restrict__ A,
    const float* __restrict__ Wq, const float* __restrict__ Wk, const float* __restrict__ Wv,
    const float* __restrict__ bq, const float* __restrict__ bk, const float* __restrict__ bv,
    float* __restrict__ Oq, float* __restrict__ Ok, float* __restrict__ Ov)
{
    extern __shared__ float sm[];
    const float* W; const float* bias; float* C;
    if (blockIdx.z == 0)      { W = Wq; bias = bq; C = Oq; }
    else if (blockIdx.z == 1) { W = Wk; bias = bk; C = Ok; }
    else                      { W = Wv; bias = bv; C = Ov; }
    gemm_tf32_body(A, W, bias, C, MTOK, DD, DD, 0,
                   blockIdx.y * 128, blockIdx.x * 128, sm);
}

// ---------------- TF32 mma flash attention, HD=64 ---------------------------
// grid (S/64, B*H), block 128 = 4 warps. Warp w owns q-rows [w*16, w*16+16).
// S = Q@K^T: A=Qs[q][d], B=K (col-major k x n == Ks[key][d] natural).
// O = P@V:  A=Ps[q][key], B=V (col-major key x d == Vs[key][d] natural).
#define AQ_STR 68
#define AV_STR 72
#define ATT_SMEM ((3 * 64 * AQ_STR + 64 * AV_STR) * 4)   // 70656 bytes

__global__ __launch_bounds__(128, 2) void attn_mma_kernel(
    const float* __restrict__ Q, const float* __restrict__ K,
    const float* __restrict__ V, const int* __restrict__ amask,
    float* __restrict__ ctx)
{
    extern __shared__ float sm[];
    float* Qs = sm;                        // [64][AQ_STR]
    float* Ks = sm + 64 * AQ_STR;          // [64][AQ_STR]
    float* Ps = sm + 2 * 64 * AQ_STR;      // [64][AQ_STR]
    float* Vs = sm + 3 * 64 * AQ_STR;      // [64][AV_STR]
    __shared__ float mbias[64];

    int tid  = threadIdx.x;
    int lane = tid & 31;
    int wrp  = tid >> 5;          // 0..3
    int g    = lane >> 2;         // 0..7
    int tg   = lane & 3;          // 0..3
    int bh = blockIdx.y;
    int b = bh / HH, h = bh % HH;
    int q0 = blockIdx.x * 64;
    int r0 = wrp * 16;            // warp's local q-row base

    // stage Q once (tf32)
    size_t baseq = ((size_t)(b * SS + q0)) * DD + h * HDD;
    for (int i = tid; i < 64 * 16; i += 128) {
        int r = i >> 4, c = (i & 15) << 2;
        float4 a = *(const float4*)&Q[baseq + (size_t)r * DD + c];
        float* p = &Qs[r * AQ_STR + c];
        p[0] = __uint_as_float(f2tf32(a.x)); p[1] = __uint_as_float(f2tf32(a.y));
        p[2] = __uint_as_float(f2tf32(a.z)); p[3] = __uint_as_float(f2tf32(a.w));
    }

    float mrow[2] = {-1e30f, -1e30f};
    float lrow[2] = {0.f, 0.f};
    float O[8][4];
#pragma unroll
    for (int nt = 0; nt < 8; nt++)
#pragma unroll
        for (int e = 0; e < 4; e++) O[nt][e] = 0.f;

    for (int kc = 0; kc < SS / 64; kc++) {
        __syncthreads();   // prior chunk's reads of Ks/Vs complete (also orders Qs stage)
        int k0g = kc * 64;
        size_t basek = ((size_t)(b * SS + k0g)) * DD + h * HDD;
        for (int i = tid; i < 64 * 16; i += 128) {
            int r = i >> 4, c = (i & 15) << 2;
            float4 a = *(const float4*)&K[basek + (size_t)r * DD + c];
            float* p = &Ks[r * AQ_STR + c];
            p[0] = __uint_as_float(f2tf32(a.x)); p[1] = __uint_as_float(f2tf32(a.y));
            p[2] = __uint_as_float(f2tf32(a.z)); p[3] = __uint_as_float(f2tf32(a.w));
            float4 vv = *(const float4*)&V[basek + (size_t)r * DD + c];
            float* pv = &Vs[r * AV_STR + c];
            pv[0] = __uint_as_float(f2tf32(vv.x)); pv[1] = __uint_as_float(f2tf32(vv.y));
            pv[2] = __uint_as_float(f2tf32(vv.z)); pv[3] = __uint_as_float(f2tf32(vv.w));
        }
        if (tid < 64) mbias[tid] = amask[b * SS + k0g + tid] ? 0.f : -1e30f;
        __syncthreads();

        // ---- scores S[16 x 64] for this warp ----
        float s[8][4];
#pragma unroll
        for (int nt = 0; nt < 8; nt++)
#pragma unroll
            for (int e = 0; e < 4; e++) s[nt][e] = 0.f;
#pragma unroll
        for (int ks = 0; ks < 8; ks++) {
            int kk = ks << 3;
            uint32_t a0 = __float_as_uint(Qs[(r0 + g    ) * AQ_STR + kk + tg    ]);
            uint32_t a1 = __float_as_uint(Qs[(r0 + g + 8) * AQ_STR + kk + tg    ]);
            uint32_t a2 = __float_as_uint(Qs[(r0 + g    ) * AQ_STR + kk + tg + 4]);
            uint32_t a3 = __float_as_uint(Qs[(r0 + g + 8) * AQ_STR + kk + tg + 4]);
#pragma unroll
            for (int nt = 0; nt < 8; nt++) {
                uint32_t b0 = __float_as_uint(Ks[(nt * 8 + g) * AQ_STR + kk + tg    ]);
                uint32_t b1 = __float_as_uint(Ks[(nt * 8 + g) * AQ_STR + kk + tg + 4]);
                mma_tf32(s[nt], a0, a1, a2, a3, b0, b1);
            }
        }
        // scale + mask (col = nt*8 + tg*2 + {0,1})
#pragma unroll
        for (int nt = 0; nt < 8; nt++) {
            float mb0 = mbias[nt * 8 + tg * 2];
            float mb1 = mbias[nt * 8 + tg * 2 + 1];
            s[nt][0] = s[nt][0] * 0.125f + mb0;
            s[nt][1] = s[nt][1] * 0.125f + mb1;
            s[nt][2] = s[nt][2] * 0.125f + mb0;
            s[nt][3] = s[nt][3] * 0.125f + mb1;
        }
        // ---- online softmax (rows g and g+8; stats across tg = lane bits 0,1) ----
        float mx0 = -1e30f, mx1 = -1e30f;
#pragma unroll
        for (int nt = 0; nt < 8; nt++) {
            mx0 = fmaxf(mx0, fmaxf(s[nt][0], s[nt][1]));
            mx1 = fmaxf(mx1, fmaxf(s[nt][2], s[nt][3]));
        }
        mx0 = fmaxf(mx0, __shfl_xor_sync(0xffffffffu, mx0, 1));
        mx0 = fmaxf(mx0, __shfl_xor_sync(0xffffffffu, mx0, 2));
        mx1 = fmaxf(mx1, __shfl_xor_sync(0xffffffffu, mx1, 1));
        mx1 = fmaxf(mx1, __shfl_xor_sync(0xffffffffu, mx1, 2));
        float mn0 = fmaxf(mrow[0], mx0);
        float mn1 = fmaxf(mrow[1], mx1);
        float al0 = __expf(mrow[0] - mn0);
        float al1 = __expf(mrow[1] - mn1);
        float rs0 = 0.f, rs1 = 0.f;
#pragma unroll
        for (int nt = 0; nt < 8; nt++) {
            s[nt][0] = __expf(s[nt][0] - mn0);
            s[nt][1] = __expf(s[nt][1] - mn0);
            s[nt][2] = __expf(s[nt][2] - mn1);
            s[nt][3] = __expf(s[nt][3] - mn1);
            rs0 += s[nt][0] + s[nt][1];
            rs1 += s[nt][2] + s[nt][3];
        }
        rs0 += __shfl_xor_sync(0xffffffffu, rs0, 1);
        rs0 += __shfl_xor_sync(0xffffffffu, rs0, 2);
        rs1 += __shfl_xor_sync(0xffffffffu, rs1, 1);
        rs1 += __shfl_xor_sync(0xffffffffu, rs1, 2);
        lrow[0] = lrow[0] * al0 + rs0;  mrow[0] = mn0;
        lrow[1] = lrow[1] * al1 + rs1;  mrow[1] = mn1;
#pragma unroll
        for (int nt = 0; nt < 8; nt++) {
            O[nt][0] *= al0; O[nt][1] *= al0;
            O[nt][2] *= al1; O[nt][3] *= al1;
        }
        // ---- write P (tf32) to warp-private rows, then P @ V ----
#pragma unroll
        for (int nt = 0; nt < 8; nt++) {
            int c0 = nt * 8 + tg * 2;
            Ps[(r0 + g    ) * AQ_STR + c0    ] = __uint_as_float(f2tf32(s[nt][0]));
            Ps[(r0 + g    ) * AQ_STR + c0 + 1] = __uint_as_float(f2tf32(s[nt][1]));
            Ps[(r0 + g + 8) * AQ_STR + c0    ] = __uint_as_float(f2tf32(s[nt][2]));
            Ps[(r0 + g + 8) * AQ_STR + c0 + 1] = __uint_as_float(f2tf32(s[nt][3]));
        }
        __syncwarp();
#pragma unroll
        for (int ks = 0; ks < 8; ks++) {
            int kk = ks << 3;
            uint32_t a0 = __float_as_uint(Ps[(r0 + g    ) * AQ_STR + kk + tg    ]);
            uint32_t a1 = __float_as_uint(Ps[(r0 + g + 8) * AQ_STR + kk + tg    ]);
            uint32_t a2 = __float_as_uint(Ps[(r0 + g    ) * AQ_STR + kk + tg + 4]);
            uint32_t a3 = __float_as_uint(Ps[(r0 + g + 8) * AQ_STR + kk + tg + 4]);
#pragma unroll
            for (int nt = 0; nt < 8; nt++) {
                uint32_t b0 = __float_as_uint(Vs[(kk + tg    ) * AV_STR + nt * 8 + g]);
                uint32_t b1 = __float_as_uint(Vs[(kk + tg + 4) * AV_STR + nt * 8 + g]);
                mma_tf32(O[nt], a0, a1, a2, a3, b0, b1);
            }
        }
        __syncwarp();   // P reads done before next chunk overwrites
    }
    // ---- write ctx ----
    float inv0 = 1.0f / lrow[0];
    float inv1 = 1.0f / lrow[1];
    size_t row0 = (size_t)(b * SS + q0 + r0 + g);
#pragma unroll
    for (int nt = 0; nt < 8; nt++) {
        int c0 = h * HDD + nt * 8 + tg * 2;
        *(float2*)&ctx[row0 * DD + c0]       = make_float2(O[nt][0] * inv0, O[nt][1] * inv0);
        *(float2*)&ctx[(row0 + 8) * DD + c0] = make_float2(O[nt][2] * inv1, O[nt][3] * inv1);
    }
}

// ---------------- masked mean pool + L2 normalize --------------------------
__global__ __launch_bounds__(256) void pool_kernel(
    const float* __restrict__ H, const int* __restrict__ amask,
    float* __restrict__ out)
{
    int b = blockIdx.x;
    int tid = threadIdx.x;
    float acc[3] = {0.f, 0.f, 0.f};
    float cl = 0.f;
    for (int s = tid; s < SS; s += 256) cl += (float)amask[b * SS + s];
    float cnt = blockReduceSum(cl);
    for (int s = 0; s < SS; s++) {
        if (amask[b * SS + s]) {
            size_t base = ((size_t)(b * SS + s)) * DD;
#pragma unroll
            for (int c = 0; c < 3; c++) acc[c] += H[base + tid + c * 256];
        }
    }
    float inv = 1.0f / fmaxf(cnt, 1e-6f);
    float se[3]; float lsq = 0.f;
#pragma unroll
    for (int c = 0; c < 3; c++) { se[c] = acc[c] * inv; lsq += se[c] * se[c]; }
    float ss = blockReduceSum(lsq);
    float nrm = sqrtf(ss);
    float d = 1.0f / fmaxf(nrm, 1e-12f);
#pragma unroll
    for (int c = 0; c < 3; c++) out[b * DD + tid + c * 256] = se[c] * d;
}

// ---------------- launch ----------------------------------------------------
extern "C" void kernel_launch(void* const* d_in, const int* in_sizes, int n_in,
                              void* d_out, int out_size)
{
    const int*   ids   = (const int*)  d_in[0];
    const int*   amask = (const int*)  d_in[1];
    const float* we    = (const float*)d_in[2];
    const float* pe    = (const float*)d_in[3];
    const float* te    = (const float*)d_in[4];
    const float* es    = (const float*)d_in[5];
    const float* eb    = (const float*)d_in[6];
    const float* Wq    = (const float*)d_in[7];
    const float* bq    = (const float*)d_in[8];
    const float* Wk    = (const float*)d_in[9];
    const float* bk    = (const float*)d_in[10];
    const float* Wv    = (const float*)d_in[11];
    const float* bv    = (const float*)d_in[12];
    const float* Wao   = (const float*)d_in[13];
    const float* bao   = (const float*)d_in[14];
    const float* ln1s  = (const float*)d_in[15];
    const float* ln1b  = (const float*)d_in[16];
    const float* Wi    = (const float*)d_in[17];
    const float* bi    = (const float*)d_in[18];
    const float* Wmo   = (const float*)d_in[19];
    const float* bmo   = (const float*)d_in[20];
    const float* ln2s  = (const float*)d_in[21];
    const float* ln2b  = (const float*)d_in[22];
    float* out = (float*)d_out;

    float *h, *q, *k, *v, *ctx, *tmp, *aout, *inter;
    cudaGetSymbolAddress((void**)&h,     g_h);
    cudaGetSymbolAddress((void**)&q,     g_q);
    cudaGetSymbolAddress((void**)&k,     g_k);
    cudaGetSymbolAddress((void**)&v,     g_v);
    cudaGetSymbolAddress((void**)&ctx,   g_ctx);
    cudaGetSymbolAddress((void**)&tmp,   g_tmp);
    cudaGetSymbolAddress((void**)&aout,  g_aout);
    cudaGetSymbolAddress((void**)&inter, g_int);

    cudaFuncSetAttribute(attn_mma_kernel, cudaFuncAttributeMaxDynamicSharedMemorySize, ATT_SMEM);
    cudaFuncSetAttribute(gemm_tf32_kernel, cudaFuncAttributeMaxDynamicSharedMemorySize, GSMEM);
    cudaFuncSetAttribute(gemm_tf32_qkv_kernel, cudaFuncAttributeMaxDynamicSharedMemorySize, GSMEM);

    embed_kernel<<<MTOK, 256>>>(ids, we, pe, te, es, eb, h);

    for (int l = 0; l < LL; l++) {
        const float* wq  = Wq  + (size_t)l * DD * DD;
        const float* wk  = Wk  + (size_t)l * DD * DD;
        const float* wv  = Wv  + (size_t)l * DD * DD;
        const float* wao = Wao + (size_t)l * DD * DD;
        const float* wi  = Wi  + (size_t)l * DD * FF_;
        const float* wmo = Wmo + (size_t)l * FF_ * DD;
        const float* bqL  = bq  + (size_t)l * DD;
        const float* bkL  = bk  + (size_t)l * DD;
        const float* bvL  = bv  + (size_t)l * DD;
        const float* baoL = bao + (size_t)l * DD;
        const float* biL  = bi  + (size_t)l * FF_;
        const float* bmoL = bmo + (size_t)l * DD;
        const float* l1s = ln1s + (size_t)l * DD;
        const float* l1b = ln1b + (size_t)l * DD;
        const float* l2s = ln2s + (size_t)l * DD;
        const float* l2b = ln2b + (size_t)l * DD;

        dim3 gD(DD / 128, MTOK / 128);        // (6, 64)
        dim3 gQKV(DD / 128, MTOK / 128, 3);   // (6, 64, 3)
        dim3 gF(FF_ / 128, MTOK / 128);       // (24, 64)

        gemm_tf32_qkv_kernel<<<gQKV, 256, GSMEM>>>(h, wq, wk, wv, bqL, bkL, bvL, q, k, v);

        attn_mma_kernel<<<dim3(SS / 64, BB * HH), 128, ATT_SMEM>>>(q, k, v, amask, ctx);

        gemm_tf32_kernel<<<gD, 256, GSMEM>>>(ctx, wao, baoL, tmp, MTOK, DD, DD, 0);
        add_ln_kernel<<<MTOK, 256>>>(tmp, h, l1s, l1b, aout);

        gemm_tf32_kernel<<<gF, 256, GSMEM>>>(aout,  wi,  biL,  inter, MTOK, FF_, DD, 1);
        gemm_tf32_kernel<<<gD, 256, GSMEM>>>(inter, wmo, bmoL, tmp,   MTOK, DD, FF_, 0);
        add_ln_kernel<<<MTOK, 256>>>(tmp, aout, l2s, l2b, h);
    }

    pool_kernel<<<BB, 256>>>(h, amask, out);
}